// round 6
// baseline (speedup 1.0000x reference)
#include <cuda_runtime.h>
#include <cstdint>

// ============================================================================
// FFTLongConv1D: y[b,l,d] = irfft( rfft(u[b,:,d],16384) * Hhat[(b*D+d)//B] )[4095+l]
// B=8, L=8192, D=256, K=8192, N=16384.
// Half-size complex FFT (8192-pt), 12 smem passes, packed f32x2 arithmetic
// (add/mul/fma.rn.f32x2) so each complex op is 1-2 fma-pipe instructions.
// NT=512, 2 CTAs/SM (~78 KB smem each).
// ============================================================================

#define NT 512
#define NC 8192
#define PADB(i) ((i) + ((i) >> 4))
#define SBUF 8704
#define TWN_H 2049
#define TWN_C 1025
#define B_ 8
#define D_ 256
#define L_ 8192

__device__ __align__(16) float2 g_Hhat[D_ * NC];          // 16.8 MB
__device__ __align__(16) float  g_uT[B_ * D_ * L_];       // 64 MB
__device__ __align__(16) float  g_yT[B_ * D_ * L_];       // 64 MB

// ---------------------------------------------------------------------------
// Packed complex arithmetic (f32x2). One complex = one 64-bit register pair.
// ---------------------------------------------------------------------------
typedef unsigned long long ull;
#define NEG1X2 0xBF800000BF800000ULL   // packed (-1.0f, -1.0f)

__device__ __forceinline__ ull pk2(float x, float y) {
    ull u; asm("mov.b64 %0, {%1, %2};" : "=l"(u) : "f"(x), "f"(y)); return u;
}
__device__ __forceinline__ ull f2u(float2 v) { return pk2(v.x, v.y); }
__device__ __forceinline__ float2 u2f(ull u) {
    float2 v; asm("mov.b64 {%0, %1}, %2;" : "=f"(v.x), "=f"(v.y) : "l"(u)); return v;
}

__device__ __forceinline__ float2 cadd(float2 a, float2 b) {
    ull o; asm("add.rn.f32x2 %0, %1, %2;" : "=l"(o) : "l"(f2u(a)), "l"(f2u(b)));
    return u2f(o);
}
// a - b == fma(b, -1, a)  (exact)
__device__ __forceinline__ float2 csub(float2 a, float2 b) {
    ull o; asm("fma.rn.f32x2 %0, %1, %2, %3;"
               : "=l"(o) : "l"(f2u(b)), "l"(NEG1X2), "l"(f2u(a)));
    return u2f(o);
}
// complex multiply: (ax*bx - ay*by, ax*by + ay*bx)
//   t = (ay,ay) * (-by, bx);  r = fma((ax,ax), (bx,by), t)
__device__ __forceinline__ float2 cmul(float2 a, float2 b) {
    ull t, o;
    asm("mul.rn.f32x2 %0, %1, %2;" : "=l"(t) : "l"(pk2(a.y, a.y)), "l"(pk2(-b.y, b.x)));
    asm("fma.rn.f32x2 %0, %1, %2, %3;" : "=l"(o) : "l"(pk2(a.x, a.x)), "l"(f2u(b)), "l"(t));
    return u2f(o);
}
// multiply by -i: (x,y) -> (y,-x)   (register swizzle + sign flip, alu pipe)
__device__ __forceinline__ float2 mulmi(float2 a) { return make_float2(a.y, -a.x); }

__device__ __forceinline__ void build_tw(float2* tw, int n) {
    for (int t = threadIdx.x; t < n; t += NT) {
        float sv, cv;
        sincospif(-(float)t * (1.0f / 4096.0f), &sv, &cv);  // e^{-2pi i t/8192}
        tw[t] = make_float2(cv, sv);
    }
}

// In-place DFT4 (DIF): 8 packed fp ops + 1 swizzle.
__device__ __forceinline__ void dft4(float2& a, float2& b, float2& c, float2& d) {
    float2 apc = cadd(a, c), amc = csub(a, c);
    float2 bpd = cadd(b, d), bmd = csub(b, d);
    float2 mj  = mulmi(bmd);
    a = cadd(apc, bpd);
    float2 o1 = cadd(amc, mj);
    c = csub(apc, bpd);
    d = csub(amc, mj);
    b = o1;
}

__device__ __forceinline__ void l1_full(float2 x[16]) {
#pragma unroll
    for (int m0 = 0; m0 < 4; m0++)
        dft4(x[m0], x[m0 + 4], x[m0 + 8], x[m0 + 12]);
}

// Level 1 with x[8..15] == 0: DFT4(a,b,0,0).
__device__ __forceinline__ void l1_half(float2 x[16]) {
#pragma unroll
    for (int m0 = 0; m0 < 4; m0++) {
        float2 a = x[m0], b = x[m0 + 4];
        float2 mib = mulmi(b);              // -i b = (b.y, -b.x)
        x[m0]      = cadd(a, b);
        x[m0 + 4]  = cadd(a, mib);          // a - i b
        x[m0 + 8]  = csub(a, b);
        x[m0 + 12] = csub(a, mib);          // a + i b
    }
}

// Internal twiddles: x[m0+4r] *= w16^{r*m0}  (constant cmuls).
__device__ __forceinline__ void tw_internal(float2 x[16]) {
    const float C1 = 0.92387953251128675f;
    const float S1 = 0.38268343236508977f;
    const float C2 = 0.70710678118654752f;
    x[5]  = cmul(x[5],  make_float2(C1, -S1));    // w^1
    x[6]  = cmul(x[6],  make_float2(C2, -C2));    // w^2
    x[7]  = cmul(x[7],  make_float2(S1, -C1));    // w^3
    x[9]  = cmul(x[9],  make_float2(C2, -C2));    // w^2
    x[10] = mulmi(x[10]);                         // w^4 = -i
    x[11] = cmul(x[11], make_float2(-C2, -C2));   // w^6
    x[13] = cmul(x[13], make_float2(S1, -C1));    // w^3
    x[14] = cmul(x[14], make_float2(-C2, -C2));   // w^6
    x[15] = cmul(x[15], make_float2(-C1, S1));    // w^9
}

// Level 2 + outer twiddles + scattered store.
__device__ __forceinline__ void r16_finish(float2* __restrict__ buf,
                                           const float2* __restrict__ tw,
                                           float2 x[16], int i, int sLog) {
    const int s = 1 << sLog;
    const int ps = i & ~(s - 1);
    float2 w1  = tw[ps];
    float2 w2  = cmul(w1, w1);
    float2 w3  = cmul(w2, w1);
    float2 w4  = cmul(w2, w2);
    float2 w8  = cmul(w4, w4);
    float2 w12 = cmul(w8, w4);
    const int base = (i & (s - 1)) + ((i >> sLog) << (sLog + 4));
    dft4(x[0], x[1], x[2], x[3]);
    buf[PADB(base)]           = x[0];
    buf[PADB(base + 4 * s)]   = cmul(w4,  x[1]);
    buf[PADB(base + 8 * s)]   = cmul(w8,  x[2]);
    buf[PADB(base + 12 * s)]  = cmul(w12, x[3]);
    dft4(x[4], x[5], x[6], x[7]);
    buf[PADB(base + s)]       = cmul(w1, x[4]);
    buf[PADB(base + 5 * s)]   = cmul(cmul(w4,  w1), x[5]);
    buf[PADB(base + 9 * s)]   = cmul(cmul(w8,  w1), x[6]);
    buf[PADB(base + 13 * s)]  = cmul(cmul(w12, w1), x[7]);
    dft4(x[8], x[9], x[10], x[11]);
    buf[PADB(base + 2 * s)]   = cmul(w2, x[8]);
    buf[PADB(base + 6 * s)]   = cmul(cmul(w4,  w2), x[9]);
    buf[PADB(base + 10 * s)]  = cmul(cmul(w8,  w2), x[10]);
    buf[PADB(base + 14 * s)]  = cmul(cmul(w12, w2), x[11]);
    dft4(x[12], x[13], x[14], x[15]);
    buf[PADB(base + 3 * s)]   = cmul(w3, x[12]);
    buf[PADB(base + 7 * s)]   = cmul(cmul(w4,  w3), x[13]);
    buf[PADB(base + 11 * s)]  = cmul(cmul(w8,  w3), x[14]);
    buf[PADB(base + 15 * s)]  = cmul(cmul(w12, w3), x[15]);
}

__device__ __forceinline__ void radix16_ip(float2* buf, const float2* tw, int sLog) {
    float2 x[16];
    const int i = threadIdx.x;
#pragma unroll
    for (int m = 0; m < 16; m++) x[m] = buf[PADB(i + m * 512)];
    __syncthreads();
    l1_full(x);
    tw_internal(x);
    r16_finish(buf, tw, x, i, sLog);
    __syncthreads();
}

// Stage 1 (s=1) fused with gmem load of a zero-padded row.
__device__ __forceinline__ void stage1_gmem(float2* buf, const float2* tw,
                                            const float2* __restrict__ row) {
    float2 x[16];
    const int i = threadIdx.x;
#pragma unroll
    for (int m = 0; m < 8; m++) x[m] = row[i + m * 512];
    l1_half(x);
    tw_internal(x);
    r16_finish(buf, tw, x, i, 0);
    __syncthreads();
}

// Spectral step for packed conjugate pair (ka, 8192-ka).
__device__ __forceinline__ void spectral_pair(float2 Zk, float2 Zk2, float2 Wk,
                                              float2 Hk, float2 Hk2,
                                              float2& Zca, float2& Zcb) {
    float2 E  = make_float2(0.5f * (Zk.x + Zk2.x), 0.5f * (Zk.y - Zk2.y));
    float2 Dv = make_float2(Zk.x - Zk2.x, Zk.y + Zk2.y);
    float2 O  = make_float2(0.5f * Dv.y, -0.5f * Dv.x);
    float2 WO = cmul(Wk, O);
    float2 Xk  = cadd(E, WO);
    float2 Xk2 = csub(E, WO); Xk2.y = -Xk2.y;
    float2 Yk  = cmul(Xk,  Hk);
    float2 Yk2 = cmul(Xk2, Hk2);
    float2 Ep = make_float2(0.5f * (Yk.x + Yk2.x), 0.5f * (Yk.y - Yk2.y));
    float2 Dy = make_float2(0.5f * (Yk.x - Yk2.x), 0.5f * (Yk.y + Yk2.y));
    float2 Op = make_float2(fmaf(Wk.x, Dy.x,  Wk.y * Dy.y),
                            fmaf(Wk.x, Dy.y, -(Wk.y * Dy.x)));
    Zca = make_float2(Ep.x - Op.y, -(Ep.y + Op.x));
    Zcb = make_float2(Ep.x + Op.y, Ep.y - Op.x);
}

// Fused middle pass: fwd radix-2 (s=4096) + spectral + inv radix-2 (s=1).
__device__ __forceinline__ void mid_fused(float2* buf, const float2* __restrict__ tw,
                                          const float2* __restrict__ Hrow) {
    const int tid = threadIdx.x;
    float2 A[4], Bv[4], C[4], Dd[4];
#pragma unroll
    for (int it = 0; it < 4; it++) {
        int k = tid + it * NT;
        int ka = k, kb = k + 4096, kc = 4096 - k, kd = 8192 - k;
        if (k == 0) { kc = 2048; kd = 6144; }
        A[it]  = buf[PADB(ka)];
        Bv[it] = buf[PADB(kb)];
        C[it]  = buf[PADB(kc)];
        Dd[it] = buf[PADB(kd)];
    }
    __syncthreads();
    float2 chalf; { float sv, cv; sincospif(-1.0f / 8192.0f, &sv, &cv); chalf = make_float2(cv, sv); }
#pragma unroll
    for (int it = 0; it < 4; it++) {
        int k = tid + it * NT;
        if (k == 0) {
            float2 Z0 = cadd(A[0], Bv[0]);
            float2 Z4 = csub(A[0], Bv[0]);
            float2 H0 = Hrow[0];
            float X0 = Z0.x + Z0.y, XN = Z0.x - Z0.y;
            float Y0 = X0 * H0.x,   YN = XN * H0.y;
            float2 Zc0 = make_float2(0.5f * (Y0 + YN), -0.5f * (Y0 - YN));
            float2 Zc4a, Zc4b;
            spectral_pair(Z4, Z4, make_float2(0.f, -1.f), Hrow[4096], Hrow[4096], Zc4a, Zc4b);
            buf[PADB(0)] = cadd(Zc0, Zc4a);
            buf[PADB(1)] = csub(Zc0, Zc4a);
            float2 Z2 = cadd(C[0], Dd[0]);
            float2 Z6 = csub(C[0], Dd[0]);
            const float rh = 0.70710678118654752f;
            float2 Zca, Zcb;
            spectral_pair(Z2, Z6, make_float2(rh, -rh), Hrow[2048], Hrow[6144], Zca, Zcb);
            float2 d = csub(Zca, Zcb);
            buf[PADB(4096)] = cadd(Zca, Zcb);
            buf[PADB(4097)] = mulmi(d);
        } else {
            float2 Zk  = cadd(A[it], Bv[it]);
            float2 Zp  = csub(A[it], Bv[it]);
            float2 Zm  = cadd(C[it], Dd[it]);
            float2 Zk2 = csub(C[it], Dd[it]);
            float2 Wk = tw[k >> 1];
            if (k & 1) Wk = cmul(Wk, chalf);
            float2 Zca, Zcb, Zcc, Zcd;
            spectral_pair(Zk, Zk2, Wk, Hrow[k], Hrow[8192 - k], Zca, Zcb);
            float2 Wm = make_float2(-Wk.y, -Wk.x);
            spectral_pair(Zm, Zp, Wm, Hrow[4096 - k], Hrow[4096 + k], Zcc, Zcd);
            float2 v  = cmul(Wk, Wk);
            float2 d1 = csub(Zca, Zcd);
            buf[PADB(2 * k)]     = cadd(Zca, Zcd);
            buf[PADB(2 * k + 1)] = cmul(v, d1);
            float2 vp = make_float2(-v.x, v.y);
            float2 d2 = csub(Zcc, Zcb);
            buf[PADB(8192 - 2 * k)] = cadd(Zcc, Zcb);
            buf[PADB(8193 - 2 * k)] = cmul(vp, d2);
        }
    }
    __syncthreads();
}

// Last inverse stage (s=512, no outer twiddles) fused with extraction.
__device__ __forceinline__ void last16_extract(const float2* __restrict__ buf,
                                               float* __restrict__ yrow) {
    float2 x[16];
    const int i = threadIdx.x;
#pragma unroll
    for (int m = 0; m < 16; m++) x[m] = buf[PADB(i + m * 512)];
    l1_full(x);
    tw_internal(x);
    const float invN = 1.0f / 8192.0f;
#pragma unroll
    for (int r = 0; r < 4; r++) {
        dft4(x[4 * r], x[4 * r + 1], x[4 * r + 2], x[4 * r + 3]);
#pragma unroll
        for (int t = 0; t < 4; t++) {
            int j = r + 4 * t;
            int tp = i + 512 * j;
            if (tp >= 2047 && tp <= 6143) {
                float2 R = x[4 * r + t];
                int la = 2 * tp - 4095;
                if (la >= 0)     yrow[la]     =  R.x * invN;
                if (la + 1 < L_) yrow[la + 1] = -R.y * invN;
            }
        }
    }
}

// ============================================================================
// Filter spectra.
// ============================================================================
__global__ void __launch_bounds__(NT, 2) hfft_kernel(const float* __restrict__ h) {
    extern __shared__ float2 sm[];
    float2* buf = sm;
    float2* tw  = sm + SBUF;
    int dIdx = blockIdx.x;
    build_tw(tw, TWN_H);
    __syncthreads();
    stage1_gmem(buf, tw, (const float2*)(h + (size_t)dIdx * 8192));
    radix16_ip(buf, tw, 4);
    radix16_ip(buf, tw, 8);

    float2* out = g_Hhat + (size_t)dIdx * NC;
    float2 chalf; { float sv, cv; sincospif(-1.0f / 8192.0f, &sv, &cv); chalf = make_float2(cv, sv); }
    for (int k = threadIdx.x; k <= 4096; k += NT) {
        if (k == 0) {
            float2 Z0 = cadd(buf[PADB(0)], buf[PADB(4096)]);
            out[0] = make_float2(Z0.x + Z0.y, Z0.x - Z0.y);
        } else {
            int k2 = 8192 - k;
            float2 Zk  = (k < 4096) ? cadd(buf[PADB(k)], buf[PADB(k + 4096)])
                                    : csub(buf[PADB(0)], buf[PADB(4096)]);
            float2 Zk2 = csub(buf[PADB(4096 - k)], buf[PADB(8192 - k)]);
            float2 E  = make_float2(0.5f * (Zk.x + Zk2.x), 0.5f * (Zk.y - Zk2.y));
            float2 Dv = make_float2(Zk.x - Zk2.x, Zk.y + Zk2.y);
            float2 O  = make_float2(0.5f * Dv.y, -0.5f * Dv.x);
            float2 Wk = tw[k >> 1];
            if (k & 1) Wk = cmul(Wk, chalf);
            float2 WO = cmul(Wk, O);
            out[k] = cadd(E, WO);
            if (k < 4096) {
                float2 o2 = csub(E, WO);
                out[k2] = make_float2(o2.x, -o2.y);
            }
        }
    }
}

// ============================================================================
// Transposes: (B, L, D) <-> row-contiguous (B*D, L)
// ============================================================================
#define TP 65

__global__ void transpose_in(const float* __restrict__ u) {
    __shared__ float tile[32][TP];
    int b  = blockIdx.z;
    int d0 = blockIdx.x * 64;
    int l0 = blockIdx.y * 32;
    int x = threadIdx.x, y = threadIdx.y;
    const float* ub = u + (size_t)b * L_ * D_;
#pragma unroll
    for (int j = 0; j < 4; j++) {
        int l = l0 + y + j * 8;
        float2 v = *(const float2*)(ub + (size_t)l * D_ + d0 + 2 * x);
        tile[y + j * 8][2 * x]     = v.x;
        tile[y + j * 8][2 * x + 1] = v.y;
    }
    __syncthreads();
#pragma unroll
    for (int j = 0; j < 8; j++) {
        int dd = y + j * 8;
        g_uT[(size_t)(b * D_ + d0 + dd) * L_ + l0 + x] = tile[x][dd];
    }
}

__global__ void transpose_out(float* __restrict__ y_out) {
    __shared__ float tile[32][TP];
    int b  = blockIdx.z;
    int d0 = blockIdx.x * 64;
    int l0 = blockIdx.y * 32;
    int x = threadIdx.x, y = threadIdx.y;
#pragma unroll
    for (int j = 0; j < 8; j++) {
        int dd = y + j * 8;
        tile[x][dd] = g_yT[(size_t)(b * D_ + d0 + dd) * L_ + l0 + x];
    }
    __syncthreads();
    float* yb = y_out + (size_t)b * L_ * D_;
#pragma unroll
    for (int j = 0; j < 4; j++) {
        int l = l0 + y + j * 8;
        float2 v = make_float2(tile[y + j * 8][2 * x], tile[y + j * 8][2 * x + 1]);
        *(float2*)(yb + (size_t)l * D_ + d0 + 2 * x) = v;
    }
}

// ============================================================================
// Per-row conv: 12 smem passes.
// ============================================================================
__global__ void __launch_bounds__(NT, 2) conv_kernel() {
    extern __shared__ float2 sm[];
    float2* buf = sm;
    float2* tw  = sm + SBUF;
    int r = blockIdx.x;             // r = b*256 + d
    int f = r >> 3;                 // filter index = (b*D+d)//B  (B=8)

    build_tw(tw, TWN_C);
    __syncthreads();

    stage1_gmem(buf, tw, (const float2*)(g_uT + (size_t)r * L_));
    radix16_ip(buf, tw, 4);
    radix16_ip(buf, tw, 8);

    mid_fused(buf, tw, g_Hhat + (size_t)f * NC);

    radix16_ip(buf, tw, 1);
    radix16_ip(buf, tw, 5);
    last16_extract(buf, g_yT + (size_t)r * L_);
}

// ============================================================================
extern "C" void kernel_launch(void* const* d_in, const int* in_sizes, int n_in,
                              void* d_out, int out_size) {
    const float* u = (const float*)d_in[0];   // (8, 8192, 256)
    const float* h = (const float*)d_in[1];   // (256, 8192)
    float* out = (float*)d_out;               // (8, 8192, 256)

    size_t smem_h = (size_t)(SBUF + TWN_H) * sizeof(float2);
    size_t smem_c = (size_t)(SBUF + TWN_C) * sizeof(float2);
    cudaFuncSetAttribute(hfft_kernel, cudaFuncAttributeMaxDynamicSharedMemorySize, (int)smem_h);
    cudaFuncSetAttribute(conv_kernel, cudaFuncAttributeMaxDynamicSharedMemorySize, (int)smem_c);

    dim3 tb(32, 8);
    hfft_kernel<<<D_, NT, smem_h>>>(h);
    transpose_in<<<dim3(D_ / 64, L_ / 32, B_), tb>>>(u);
    conv_kernel<<<B_ * D_, NT, smem_c>>>();
    transpose_out<<<dim3(D_ / 64, L_ / 32, B_), tb>>>(out);
    (void)in_sizes; (void)n_in; (void)out_size;
}